// round 2
// baseline (speedup 1.0000x reference)
#include <cuda_runtime.h>
#include <math.h>
#include <stdint.h>

// ============================================================================
// OpenMaxSeparation (round 2): exact fp32, pipelined SGEMM + row-min
//   out[0 .. B)       = mask_novel as float 0/1
//   out[B .. B + B*C) = softmax(predictions)
// ============================================================================

#define BM 128
#define BN 128
#define BK 16
#define TM 8
#define TN 8
#define CSPLIT 2
#define MAXB 16384
#define MAXCP 2048

__device__ float g_f2[MAXB];
__device__ float g_c2[MAXCP];
__device__ float g_part[CSPLIT * MAXB];

// ---------------------------------------------------------------- row ||f||^2
__global__ void f2_kernel(const float* __restrict__ A, int D) {
    int row = blockIdx.x;
    const float4* a4 = reinterpret_cast<const float4*>(A + (size_t)row * D);
    int n4 = D >> 2;
    float s = 0.f;
    for (int i = threadIdx.x; i < n4; i += blockDim.x) {
        float4 v = a4[i];
        s += v.x * v.x + v.y * v.y + v.z * v.z + v.w * v.w;
    }
#pragma unroll
    for (int o = 16; o; o >>= 1) s += __shfl_down_sync(0xffffffffu, s, o);
    __shared__ float sm[4];
    if ((threadIdx.x & 31) == 0) sm[threadIdx.x >> 5] = s;
    __syncthreads();
    if (threadIdx.x == 0) g_f2[row] = sm[0] + sm[1] + sm[2] + sm[3];
}

// ---------------------------------------------------------- class ||c||^2/INF
__global__ void c2_kernel(const float* __restrict__ Cen, int C, int D) {
    int c = blockIdx.x;
    if (c >= C) {
        if (threadIdx.x == 0) g_c2[c] = 3.0e38f;
        return;
    }
    const float4* a4 = reinterpret_cast<const float4*>(Cen + (size_t)c * D);
    int n4 = D >> 2;
    float s = 0.f;
    for (int i = threadIdx.x; i < n4; i += blockDim.x) {
        float4 v = a4[i];
        s += v.x * v.x + v.y * v.y + v.z * v.z + v.w * v.w;
    }
#pragma unroll
    for (int o = 16; o; o >>= 1) s += __shfl_down_sync(0xffffffffu, s, o);
    __shared__ float sm[4];
    if ((threadIdx.x & 31) == 0) sm[threadIdx.x >> 5] = s;
    __syncthreads();
    if (threadIdx.x == 0) g_c2[c] = sm[0] + sm[1] + sm[2] + sm[3];
}

// ------------------------------------------------------------------- softmax
// One block (128 threads) per row; C <= 1024 (C = 1000 here).
__global__ void softmax_kernel(const float* __restrict__ P,
                               float* __restrict__ out, int C) {
    int row = blockIdx.x;
    const float* p = P + (size_t)row * C;
    float* o = out + (size_t)row * C;
    int tid = threadIdx.x;

    float v[8];
    float m = -3.4e38f;
#pragma unroll
    for (int i = 0; i < 8; i++) {
        int j = tid + i * 128;
        v[i] = (j < C) ? p[j] : -3.4e38f;
        m = fmaxf(m, v[i]);
    }
#pragma unroll
    for (int o2 = 16; o2; o2 >>= 1) m = fmaxf(m, __shfl_xor_sync(0xffffffffu, m, o2));
    __shared__ float smax[4];
    if ((tid & 31) == 0) smax[tid >> 5] = m;
    __syncthreads();
    m = fmaxf(fmaxf(smax[0], smax[1]), fmaxf(smax[2], smax[3]));

    float s = 0.f;
#pragma unroll
    for (int i = 0; i < 8; i++) {
        int j = tid + i * 128;
        if (j < C) {
            v[i] = expf(v[i] - m);
            s += v[i];
        }
    }
#pragma unroll
    for (int o2 = 16; o2; o2 >>= 1) s += __shfl_xor_sync(0xffffffffu, s, o2);
    __shared__ float ssum[4];
    if ((tid & 31) == 0) ssum[tid >> 5] = s;
    __syncthreads();
    s = ssum[0] + ssum[1] + ssum[2] + ssum[3];
    float inv = 1.0f / s;
#pragma unroll
    for (int i = 0; i < 8; i++) {
        int j = tid + i * 128;
        if (j < C) o[j] = v[i] * inv;
    }
}

// --------------------------------------------- pipelined SGEMM + row-min d2
// grid = (B/BM, CSPLIT). Each block: 128 rows x CP/CSPLIT classes.
// Running min of (c2 - 2*cross) per row; f2 added in mask kernel.
__global__ void __launch_bounds__(256)
distmin_kernel(const float* __restrict__ A, const float* __restrict__ Cen,
               int B, int C, int D, int CP) {
    __shared__ __align__(16) float As[2][BK][BM + 4];
    __shared__ __align__(16) float Bs[2][BK][BN + 4];

    const int tid = threadIdx.x;
    const int tx = tid & 15;   // class-group 0..15
    const int ty = tid >> 4;   // row-group   0..15
    const int rowBase = blockIdx.x * BM;
    const int cHalf = CP / CSPLIT;
    const int cBase = blockIdx.y * cHalf;

    // per-thread load coords: two float4 per tile per matrix
    const int r0 = tid >> 1;               // rows 0..127 (threads paired)
    const int kv0 = (tid & 1) << 3;        // k offset 0 or 8 (two float4 each)

    float minv[TM];
#pragma unroll
    for (int i = 0; i < TM; i++) minv[i] = 3.0e38f;

    const int KT = D / BK;  // 128 k-tiles

    for (int cc = 0; cc < cHalf; cc += BN) {
        const int c0 = cBase + cc;
        float acc[TM][TN];
#pragma unroll
        for (int i = 0; i < TM; i++)
#pragma unroll
            for (int j = 0; j < TN; j++) acc[i][j] = 0.f;

        // ---- prologue: load k-tile 0 into buffer 0
        {
            const float* arow = A + (size_t)(rowBase + r0) * D + kv0;
            float4 a0 = *reinterpret_cast<const float4*>(arow);
            float4 a1 = *reinterpret_cast<const float4*>(arow + 4);
            int c = c0 + r0;
            float4 b0 = make_float4(0.f, 0.f, 0.f, 0.f), b1 = b0;
            if (c < C) {
                const float* brow = Cen + (size_t)c * D + kv0;
                b0 = *reinterpret_cast<const float4*>(brow);
                b1 = *reinterpret_cast<const float4*>(brow + 4);
            }
            As[0][kv0 + 0][r0] = a0.x; As[0][kv0 + 1][r0] = a0.y;
            As[0][kv0 + 2][r0] = a0.z; As[0][kv0 + 3][r0] = a0.w;
            As[0][kv0 + 4][r0] = a1.x; As[0][kv0 + 5][r0] = a1.y;
            As[0][kv0 + 6][r0] = a1.z; As[0][kv0 + 7][r0] = a1.w;
            Bs[0][kv0 + 0][r0] = b0.x; Bs[0][kv0 + 1][r0] = b0.y;
            Bs[0][kv0 + 2][r0] = b0.z; Bs[0][kv0 + 3][r0] = b0.w;
            Bs[0][kv0 + 4][r0] = b1.x; Bs[0][kv0 + 5][r0] = b1.y;
            Bs[0][kv0 + 6][r0] = b1.z; Bs[0][kv0 + 7][r0] = b1.w;
        }
        __syncthreads();

        for (int t = 0; t < KT; t++) {
            const int cur = t & 1;
            const int nxt = cur ^ 1;

            // ---- prefetch next k-tile into registers (overlaps compute)
            float4 pa0, pa1, pb0, pb1;
            const bool more = (t + 1 < KT);
            if (more) {
                const int k0 = (t + 1) * BK;
                const float* arow = A + (size_t)(rowBase + r0) * D + k0 + kv0;
                pa0 = *reinterpret_cast<const float4*>(arow);
                pa1 = *reinterpret_cast<const float4*>(arow + 4);
                int c = c0 + r0;
                pb0 = make_float4(0.f, 0.f, 0.f, 0.f); pb1 = pb0;
                if (c < C) {
                    const float* brow = Cen + (size_t)c * D + k0 + kv0;
                    pb0 = *reinterpret_cast<const float4*>(brow);
                    pb1 = *reinterpret_cast<const float4*>(brow + 4);
                }
            }

            // ---- compute current tile
#pragma unroll
            for (int k = 0; k < BK; k++) {
                float4 a0 = *reinterpret_cast<const float4*>(&As[cur][k][ty * TM]);
                float4 a1 = *reinterpret_cast<const float4*>(&As[cur][k][ty * TM + 4]);
                float4 b0 = *reinterpret_cast<const float4*>(&Bs[cur][k][tx * TN]);
                float4 b1 = *reinterpret_cast<const float4*>(&Bs[cur][k][tx * TN + 4]);
                float a[TM] = {a0.x, a0.y, a0.z, a0.w, a1.x, a1.y, a1.z, a1.w};
                float b[TN] = {b0.x, b0.y, b0.z, b0.w, b1.x, b1.y, b1.z, b1.w};
#pragma unroll
                for (int i = 0; i < TM; i++)
#pragma unroll
                    for (int j = 0; j < TN; j++)
                        acc[i][j] = fmaf(a[i], b[j], acc[i][j]);
            }

            // ---- store prefetched tile
            if (more) {
                As[nxt][kv0 + 0][r0] = pa0.x; As[nxt][kv0 + 1][r0] = pa0.y;
                As[nxt][kv0 + 2][r0] = pa0.z; As[nxt][kv0 + 3][r0] = pa0.w;
                As[nxt][kv0 + 4][r0] = pa1.x; As[nxt][kv0 + 5][r0] = pa1.y;
                As[nxt][kv0 + 6][r0] = pa1.z; As[nxt][kv0 + 7][r0] = pa1.w;
                Bs[nxt][kv0 + 0][r0] = pb0.x; Bs[nxt][kv0 + 1][r0] = pb0.y;
                Bs[nxt][kv0 + 2][r0] = pb0.z; Bs[nxt][kv0 + 3][r0] = pb0.w;
                Bs[nxt][kv0 + 4][r0] = pb1.x; Bs[nxt][kv0 + 5][r0] = pb1.y;
                Bs[nxt][kv0 + 6][r0] = pb1.z; Bs[nxt][kv0 + 7][r0] = pb1.w;
            }
            __syncthreads();
        }

        // ---- epilogue: d2' = c2[c] - 2*cross, running row min
#pragma unroll
        for (int j = 0; j < TN; j++) {
            int c = c0 + tx * TN + j;
            float c2 = g_c2[c];
#pragma unroll
            for (int i = 0; i < TM; i++) {
                float d2 = fmaf(-2.f, acc[i][j], c2);
                minv[i] = fminf(minv[i], d2);
            }
        }
        __syncthreads();
    }

    // reduce min across the 16 tx threads sharing each row
#pragma unroll
    for (int i = 0; i < TM; i++) {
        float v = minv[i];
#pragma unroll
        for (int o = 8; o; o >>= 1)
            v = fminf(v, __shfl_xor_sync(0xffffffffu, v, o, 16));
        if (tx == 0) {
            int row = rowBase + ty * TM + i;
            g_part[blockIdx.y * B + row] = v;
        }
    }
}

// ----------------------------------------------------------------- threshold
__global__ void mask_kernel(const float* __restrict__ gs,
                            float* __restrict__ out, int B) {
    int b = blockIdx.x * blockDim.x + threadIdx.x;
    if (b >= B) return;
    float thr = gs[0] + 1.5f * gs[1];
    float m = fminf(g_part[b], g_part[B + b]) + g_f2[b];
    float md = sqrtf(fmaxf(m, 0.f));
    float score = md / (thr + 1e-8f);
    out[b] = (score > 1.0f) ? 1.0f : 0.0f;
}

// ============================================================================
extern "C" void kernel_launch(void* const* d_in, const int* in_sizes, int n_in,
                              void* d_out, int out_size) {
    const float* features    = (const float*)d_in[0];  // [B, D]
    const float* predictions = (const float*)d_in[1];  // [B, C]
    const float* centers     = (const float*)d_in[2];  // [C, D]
    const float* gstats      = (const float*)d_in[3];  // [2]
    // d_in[4] = known_labels (int64, unused), d_in[5] = num_known_classes (unused)

    int B = in_sizes[4];          // known_labels element count
    int C = in_sizes[1] / B;
    int D = in_sizes[0] / B;
    int CP = ((C + BN - 1) / BN) * BN;      // 1024
    if (CP % (BN * CSPLIT) != 0) CP = ((CP + BN * CSPLIT - 1) / (BN * CSPLIT)) * (BN * CSPLIT);

    float* out = (float*)d_out;
    float* mask_out  = out;       // [B]
    float* probs_out = out + B;   // [B, C]

    f2_kernel<<<B, 128>>>(features, D);
    c2_kernel<<<CP, 128>>>(centers, C, D);
    softmax_kernel<<<B, 128>>>(predictions, probs_out, C);
    dim3 grid(B / BM, CSPLIT);
    distmin_kernel<<<grid, 256>>>(features, centers, B, C, D, CP);
    mask_kernel<<<(B + 255) / 256, 256>>>(gstats, mask_out, B);
}

// round 3
// speedup vs baseline: 1.4137x; 1.4137x over previous
#include <cuda_runtime.h>
#include <math.h>
#include <stdint.h>

// ============================================================================
// OpenMaxSeparation (round 3): exact fp32, occupancy-fixed SGEMM + row-min
//   out[0 .. B)       = mask_novel as float 0/1
//   out[B .. B + B*C) = softmax(predictions)
// Change vs r2: __launch_bounds__(256,2) (2 CTA/SM), CSPLIT=8 (1024 CTAs,
// one 128-class tile per CTA over full K), partial mins in g_part[8][B].
// ============================================================================

#define BM 128
#define BN 128
#define BK 16
#define TM 8
#define TN 8
#define CSPLIT 8
#define MAXB 16384
#define MAXCP 2048

__device__ float g_f2[MAXB];
__device__ float g_c2[MAXCP];
__device__ float g_part[CSPLIT * MAXB];

// ---------------------------------------------------------------- row ||f||^2
__global__ void f2_kernel(const float* __restrict__ A, int D) {
    int row = blockIdx.x;
    const float4* a4 = reinterpret_cast<const float4*>(A + (size_t)row * D);
    int n4 = D >> 2;
    float s = 0.f;
    for (int i = threadIdx.x; i < n4; i += blockDim.x) {
        float4 v = a4[i];
        s += v.x * v.x + v.y * v.y + v.z * v.z + v.w * v.w;
    }
#pragma unroll
    for (int o = 16; o; o >>= 1) s += __shfl_down_sync(0xffffffffu, s, o);
    __shared__ float sm[4];
    if ((threadIdx.x & 31) == 0) sm[threadIdx.x >> 5] = s;
    __syncthreads();
    if (threadIdx.x == 0) g_f2[row] = sm[0] + sm[1] + sm[2] + sm[3];
}

// ---------------------------------------------------------- class ||c||^2/INF
__global__ void c2_kernel(const float* __restrict__ Cen, int C, int D) {
    int c = blockIdx.x;
    if (c >= C) {
        if (threadIdx.x == 0) g_c2[c] = 3.0e38f;
        return;
    }
    const float4* a4 = reinterpret_cast<const float4*>(Cen + (size_t)c * D);
    int n4 = D >> 2;
    float s = 0.f;
    for (int i = threadIdx.x; i < n4; i += blockDim.x) {
        float4 v = a4[i];
        s += v.x * v.x + v.y * v.y + v.z * v.z + v.w * v.w;
    }
#pragma unroll
    for (int o = 16; o; o >>= 1) s += __shfl_down_sync(0xffffffffu, s, o);
    __shared__ float sm[4];
    if ((threadIdx.x & 31) == 0) sm[threadIdx.x >> 5] = s;
    __syncthreads();
    if (threadIdx.x == 0) g_c2[c] = sm[0] + sm[1] + sm[2] + sm[3];
}

// ------------------------------------------------------------------- softmax
// One block (128 threads) per row; C <= 1024 (C = 1000 here).
__global__ void softmax_kernel(const float* __restrict__ P,
                               float* __restrict__ out, int C) {
    int row = blockIdx.x;
    const float* p = P + (size_t)row * C;
    float* o = out + (size_t)row * C;
    int tid = threadIdx.x;

    float v[8];
    float m = -3.4e38f;
#pragma unroll
    for (int i = 0; i < 8; i++) {
        int j = tid + i * 128;
        v[i] = (j < C) ? p[j] : -3.4e38f;
        m = fmaxf(m, v[i]);
    }
#pragma unroll
    for (int o2 = 16; o2; o2 >>= 1) m = fmaxf(m, __shfl_xor_sync(0xffffffffu, m, o2));
    __shared__ float smax[4];
    if ((tid & 31) == 0) smax[tid >> 5] = m;
    __syncthreads();
    m = fmaxf(fmaxf(smax[0], smax[1]), fmaxf(smax[2], smax[3]));

    float s = 0.f;
#pragma unroll
    for (int i = 0; i < 8; i++) {
        int j = tid + i * 128;
        if (j < C) {
            v[i] = expf(v[i] - m);
            s += v[i];
        }
    }
#pragma unroll
    for (int o2 = 16; o2; o2 >>= 1) s += __shfl_xor_sync(0xffffffffu, s, o2);
    __shared__ float ssum[4];
    if ((tid & 31) == 0) ssum[tid >> 5] = s;
    __syncthreads();
    s = ssum[0] + ssum[1] + ssum[2] + ssum[3];
    float inv = 1.0f / s;
#pragma unroll
    for (int i = 0; i < 8; i++) {
        int j = tid + i * 128;
        if (j < C) o[j] = v[i] * inv;
    }
}

// --------------------------------------------- pipelined SGEMM + row-min d2
// grid = (B/BM, CSPLIT). Each block: 128 rows x ONE 128-class tile, full K.
// Running min of (c2 - 2*cross) per row; f2 added in mask kernel.
__global__ void __launch_bounds__(256, 2)
distmin_kernel(const float* __restrict__ A, const float* __restrict__ Cen,
               int B, int C, int D) {
    __shared__ __align__(16) float As[2][BK][BM + 4];
    __shared__ __align__(16) float Bs[2][BK][BN + 4];

    const int tid = threadIdx.x;
    const int tx = tid & 15;   // class-group 0..15
    const int ty = tid >> 4;   // row-group   0..15
    const int rowBase = blockIdx.x * BM;
    const int c0 = blockIdx.y * BN;

    // per-thread load coords: two float4 per tile per matrix
    const int r0 = tid >> 1;               // rows 0..127 (threads paired)
    const int kv0 = (tid & 1) << 3;        // k offset 0 or 8 (two float4 each)

    const int cLoad = c0 + r0;
    const bool cValid = (cLoad < C);
    const float* aBase = A + (size_t)(rowBase + r0) * D + kv0;
    const float* bBase = Cen + (size_t)(cValid ? cLoad : 0) * D + kv0;

    float acc[TM][TN];
#pragma unroll
    for (int i = 0; i < TM; i++)
#pragma unroll
        for (int j = 0; j < TN; j++) acc[i][j] = 0.f;

    const int KT = D / BK;  // 128 k-tiles

    // ---- prologue: load k-tile 0 into buffer 0
    {
        float4 a0 = *reinterpret_cast<const float4*>(aBase);
        float4 a1 = *reinterpret_cast<const float4*>(aBase + 4);
        float4 b0 = make_float4(0.f, 0.f, 0.f, 0.f), b1 = b0;
        if (cValid) {
            b0 = *reinterpret_cast<const float4*>(bBase);
            b1 = *reinterpret_cast<const float4*>(bBase + 4);
        }
        As[0][kv0 + 0][r0] = a0.x; As[0][kv0 + 1][r0] = a0.y;
        As[0][kv0 + 2][r0] = a0.z; As[0][kv0 + 3][r0] = a0.w;
        As[0][kv0 + 4][r0] = a1.x; As[0][kv0 + 5][r0] = a1.y;
        As[0][kv0 + 6][r0] = a1.z; As[0][kv0 + 7][r0] = a1.w;
        Bs[0][kv0 + 0][r0] = b0.x; Bs[0][kv0 + 1][r0] = b0.y;
        Bs[0][kv0 + 2][r0] = b0.z; Bs[0][kv0 + 3][r0] = b0.w;
        Bs[0][kv0 + 4][r0] = b1.x; Bs[0][kv0 + 5][r0] = b1.y;
        Bs[0][kv0 + 6][r0] = b1.z; Bs[0][kv0 + 7][r0] = b1.w;
    }
    __syncthreads();

    for (int t = 0; t < KT; t++) {
        const int cur = t & 1;
        const int nxt = cur ^ 1;

        // ---- prefetch next k-tile into registers (overlaps compute)
        float4 pa0, pa1, pb0, pb1;
        const bool more = (t + 1 < KT);
        if (more) {
            const int k0 = (t + 1) * BK;
            pa0 = *reinterpret_cast<const float4*>(aBase + k0);
            pa1 = *reinterpret_cast<const float4*>(aBase + k0 + 4);
            pb0 = make_float4(0.f, 0.f, 0.f, 0.f); pb1 = pb0;
            if (cValid) {
                pb0 = *reinterpret_cast<const float4*>(bBase + k0);
                pb1 = *reinterpret_cast<const float4*>(bBase + k0 + 4);
            }
        }

        // ---- compute current tile
#pragma unroll
        for (int k = 0; k < BK; k++) {
            float4 a0 = *reinterpret_cast<const float4*>(&As[cur][k][ty * TM]);
            float4 a1 = *reinterpret_cast<const float4*>(&As[cur][k][ty * TM + 4]);
            float4 b0 = *reinterpret_cast<const float4*>(&Bs[cur][k][tx * TN]);
            float4 b1 = *reinterpret_cast<const float4*>(&Bs[cur][k][tx * TN + 4]);
            float a[TM] = {a0.x, a0.y, a0.z, a0.w, a1.x, a1.y, a1.z, a1.w};
            float b[TN] = {b0.x, b0.y, b0.z, b0.w, b1.x, b1.y, b1.z, b1.w};
#pragma unroll
            for (int i = 0; i < TM; i++)
#pragma unroll
                for (int j = 0; j < TN; j++)
                    acc[i][j] = fmaf(a[i], b[j], acc[i][j]);
        }

        // ---- store prefetched tile
        if (more) {
            As[nxt][kv0 + 0][r0] = pa0.x; As[nxt][kv0 + 1][r0] = pa0.y;
            As[nxt][kv0 + 2][r0] = pa0.z; As[nxt][kv0 + 3][r0] = pa0.w;
            As[nxt][kv0 + 4][r0] = pa1.x; As[nxt][kv0 + 5][r0] = pa1.y;
            As[nxt][kv0 + 6][r0] = pa1.z; As[nxt][kv0 + 7][r0] = pa1.w;
            Bs[nxt][kv0 + 0][r0] = pb0.x; Bs[nxt][kv0 + 1][r0] = pb0.y;
            Bs[nxt][kv0 + 2][r0] = pb0.z; Bs[nxt][kv0 + 3][r0] = pb0.w;
            Bs[nxt][kv0 + 4][r0] = pb1.x; Bs[nxt][kv0 + 5][r0] = pb1.y;
            Bs[nxt][kv0 + 6][r0] = pb1.z; Bs[nxt][kv0 + 7][r0] = pb1.w;
        }
        __syncthreads();
    }

    // ---- epilogue: d2' = c2[c] - 2*cross, row min over this class tile
    float minv[TM];
#pragma unroll
    for (int i = 0; i < TM; i++) minv[i] = 3.0e38f;
#pragma unroll
    for (int j = 0; j < TN; j++) {
        int c = c0 + tx * TN + j;
        float c2 = g_c2[c];
#pragma unroll
        for (int i = 0; i < TM; i++) {
            float d2 = fmaf(-2.f, acc[i][j], c2);
            minv[i] = fminf(minv[i], d2);
        }
    }

    // reduce min across the 16 tx threads sharing each row
#pragma unroll
    for (int i = 0; i < TM; i++) {
        float v = minv[i];
#pragma unroll
        for (int o = 8; o; o >>= 1)
            v = fminf(v, __shfl_xor_sync(0xffffffffu, v, o, 16));
        if (tx == 0) {
            int row = rowBase + ty * TM + i;
            g_part[blockIdx.y * B + row] = v;
        }
    }
}

// ----------------------------------------------------------------- threshold
__global__ void mask_kernel(const float* __restrict__ gs,
                            float* __restrict__ out, int B) {
    int b = blockIdx.x * blockDim.x + threadIdx.x;
    if (b >= B) return;
    float thr = gs[0] + 1.5f * gs[1];
    float m = 3.0e38f;
#pragma unroll
    for (int s = 0; s < CSPLIT; s++) m = fminf(m, g_part[s * B + b]);
    m += g_f2[b];
    float md = sqrtf(fmaxf(m, 0.f));
    float score = md / (thr + 1e-8f);
    out[b] = (score > 1.0f) ? 1.0f : 0.0f;
}

// ============================================================================
extern "C" void kernel_launch(void* const* d_in, const int* in_sizes, int n_in,
                              void* d_out, int out_size) {
    const float* features    = (const float*)d_in[0];  // [B, D]
    const float* predictions = (const float*)d_in[1];  // [B, C]
    const float* centers     = (const float*)d_in[2];  // [C, D]
    const float* gstats      = (const float*)d_in[3];  // [2]
    // d_in[4] = known_labels (int64, unused), d_in[5] = num_known_classes (unused)

    int B = in_sizes[4];          // known_labels element count
    int C = in_sizes[1] / B;
    int D = in_sizes[0] / B;
    int CP = BN * CSPLIT;         // 1024 padded classes

    float* out = (float*)d_out;
    float* mask_out  = out;       // [B]
    float* probs_out = out + B;   // [B, C]

    f2_kernel<<<B, 128>>>(features, D);
    c2_kernel<<<CP, 128>>>(centers, C, D);
    softmax_kernel<<<B, 128>>>(predictions, probs_out, C);
    dim3 grid(B / BM, CSPLIT);
    distmin_kernel<<<grid, 256>>>(features, centers, B, C, D);
    mask_kernel<<<(B + 255) / 256, 256>>>(gstats, mask_out, B);
}